// round 16
// baseline (speedup 1.0000x reference)
#include <cuda_runtime.h>
#include <cstdint>

#define N_SAMPLES 131072
#define M_COMP    2048
#define NPAIR     1024
#define NTILE     128                 // 16 components per tile
#define NSUP      16                  // 8 tiles per supertile
#define THREADS   128
#define GRID_MAIN (N_SAMPLES/(THREADS*2)) // 512
#define SGRID     64
#define SCELLS    4096
#define CGRID     16
#define CCELLS    256
#define SKIP_BITS 22.0f
#define SMEM_BYTES (NPAIR*12*4)       // 48 KB

typedef unsigned long long ull;

// ---- device globals ----
__device__ float  g_coef4[NPAIR*12];
__device__ float  g_fast[NPAIR*8];
__device__ float2 g_smu[M_COMP];
__device__ float  g_swl[M_COMP];
__device__ float4 g_tbb[NTILE];
__device__ float  g_twl[NTILE];
__device__ float4 g_sbb[NSUP];
__device__ float  g_swlmx[NSUP];
__device__ int    g_ctile[CCELLS];
__device__ float  g_cg[4];
__device__ float  g_quad[4];
__device__ int    g_uniform;
__device__ int    g_cellcnt[SCELLS];   // zero-init at load; self-rezeroed each call
__device__ int    g_cellcur[SCELLS];
__device__ float4 g_sphl[N_SAMPLES];   // sorted: {x, y, idx_bits, 0}

// ---------- packed f32x2 helpers ----------
__device__ __forceinline__ ull pk2(float x) {
    ull r; asm("mov.b64 %0,{%1,%1};" : "=l"(r) : "f"(x)); return r;
}
__device__ __forceinline__ ull pk2p(float lo, float hi) {
    ull r; asm("mov.b64 %0,{%1,%2};" : "=l"(r) : "f"(lo), "f"(hi)); return r;
}
__device__ __forceinline__ void unpk(ull v, float& lo, float& hi) {
    asm("mov.b64 {%0,%1},%2;" : "=f"(lo), "=f"(hi) : "l"(v));
}
__device__ __forceinline__ ull f2fma(ull a, ull b, ull c) {
    ull d; asm("fma.rn.f32x2 %0,%1,%2,%3;" : "=l"(d) : "l"(a), "l"(b), "l"(c)); return d;
}
__device__ __forceinline__ ull f2add(ull a, ull b) {
    ull d; asm("add.rn.f32x2 %0,%1,%2;" : "=l"(d) : "l"(a), "l"(b)); return d;
}
__device__ __forceinline__ float ex2(float x) {
    float y; asm("ex2.approx.ftz.f32 %0,%1;" : "=f"(y) : "f"(x)); return y;
}
__device__ __forceinline__ float lg2(float x) {
    float y; asm("lg2.approx.f32 %0,%1;" : "=f"(y) : "f"(x)); return y;
}
__device__ __forceinline__ void lds2(ull& a, ull& b, uint32_t addr) {
    asm("ld.shared.v2.b64 {%0,%1},[%2];" : "=l"(a), "=l"(b) : "r"(addr));
}
__device__ __forceinline__ ull ldsb64(uint32_t addr) {
    ull a; asm("ld.shared.b64 %0,[%1];" : "=l"(a) : "r"(addr)); return a;
}
__device__ __forceinline__ int warp_iscan(int v, int lane) {
    #pragma unroll
    for (int o = 1; o < 32; o <<= 1) {
        int u = __shfl_up_sync(0xffffffffu, v, o);
        if (lane >= o) v += u;
    }
    return v;
}

__device__ __forceinline__ int sample_cell(float x, float y) {
    int cx = min(max((int)((x + 4.0f) * 8.0f), 0), SGRID - 1);
    int cy = min(max((int)((y + 4.0f) * 8.0f), 0), SGRID - 1);
    return cy * SGRID + cx;
}

// ---------- K1: histogram (4 samples/thread) ----------
__global__ void k_hist4(const float* __restrict__ sample) {
    int idx = blockIdx.x * blockDim.x + threadIdx.x;   // 32768 threads
    const float4* s4 = (const float4*)sample;
    float4 f1 = s4[idx];
    float4 f2 = s4[idx + 32768];
    atomicAdd(&g_cellcnt[sample_cell(f1.x, f1.y)], 1);
    atomicAdd(&g_cellcnt[sample_cell(f1.z, f1.w)], 1);
    atomicAdd(&g_cellcnt[sample_cell(f2.x, f2.y)], 1);
    atomicAdd(&g_cellcnt[sample_cell(f2.z, f2.w)], 1);
}

// ---------- K2: scan (parallel) + component prep (1 block, 1024 threads) ----------
__global__ void k_prepscan(const float* __restrict__ w,
                           const float* __restrict__ mu,
                           const float* __restrict__ Am) {
    __shared__ int wsum[32];
    __shared__ float r32[32];
    __shared__ float4 bb32[32];
    __shared__ float s_mx, s_lse, s_bbox[4];
    __shared__ int s_flag;
    __shared__ int s_hist[CCELLS];
    __shared__ int s_start[CCELLS];
    __shared__ int s_cur[CCELLS];
    __shared__ int w8[8];
    __shared__ unsigned char s_cell[M_COMP];
    const float L = 1.4426950408889634f;
    int t = threadIdx.x, lane = t & 31, wid = t >> 5;

    // ---- part 1: parallel exclusive scan of g_cellcnt (4 per thread) + rezero ----
    {
        int b4 = t * 4;
        int c0 = g_cellcnt[b4], c1 = g_cellcnt[b4+1], c2 = g_cellcnt[b4+2], c3 = g_cellcnt[b4+3];
        int sum = c0 + c1 + c2 + c3;
        int isc = warp_iscan(sum, lane);
        if (lane == 31) wsum[wid] = isc;
        __syncthreads();
        if (wid == 0) {
            int v = wsum[lane];
            v = warp_iscan(v, lane);
            wsum[lane] = v;
        }
        __syncthreads();
        int wbase = (wid > 0) ? wsum[wid - 1] : 0;
        int base = wbase + isc - sum;   // exclusive
        g_cellcur[b4]   = base;
        g_cellcur[b4+1] = base + c0;
        g_cellcur[b4+2] = base + c0 + c1;
        g_cellcur[b4+3] = base + c0 + c1 + c2;
        g_cellcnt[b4] = 0; g_cellcnt[b4+1] = 0; g_cellcnt[b4+2] = 0; g_cellcnt[b4+3] = 0;
    }
    __syncthreads();

    // ---- part 2: component prep (2 comps/thread) ----
    if (t == 0) s_flag = 1;
    if (t < CCELLS) s_hist[t] = 0;

    float a = w[t], b = w[t + 1024];

    float v = fmaxf(a, b);
    #pragma unroll
    for (int o = 16; o; o >>= 1) v = fmaxf(v, __shfl_xor_sync(0xffffffffu, v, o));
    if (lane == 0) r32[wid] = v;
    __syncthreads();
    if (wid == 0) {
        float m = r32[lane];
        #pragma unroll
        for (int o = 16; o; o >>= 1) m = fmaxf(m, __shfl_xor_sync(0xffffffffu, m, o));
        if (lane == 0) s_mx = m;
    }
    __syncthreads();
    float mx = s_mx;
    float e = expf(a - mx) + expf(b - mx);
    #pragma unroll
    for (int o = 16; o; o >>= 1) e += __shfl_xor_sync(0xffffffffu, e, o);
    __syncthreads();
    if (lane == 0) r32[wid] = e;
    __syncthreads();
    if (wid == 0) {
        float s = r32[lane];
        #pragma unroll
        for (int o = 16; o; o >>= 1) s += __shfl_xor_sync(0xffffffffu, s, o);
        if (lane == 0) s_lse = mx + logf(s);
    }
    __syncthreads();
    float lse = s_lse;

    float r00 = Am[0], r01 = Am[1], r10 = Am[2], r11 = Am[3];
    float g000 = 0.5f * (r00*r00 + r01*r01);
    float g010 = 0.5f * (r00*r10 + r01*r11);
    float g110 = 0.5f * (r10*r10 + r11*r11);

    float c3v[2], c4v[2], c5v[2], m0v[2], m1v[2], wlv[2];
    bool ok = true;
    #pragma unroll
    for (int k = 0; k < 2; ++k) {
        int m = t + k * 1024;
        float a00 = Am[4*m+0], a01 = Am[4*m+1], a10 = Am[4*m+2], a11 = Am[4*m+3];
        float g00 = 0.5f * (a00*a00 + a01*a01);
        float g01 = 0.5f * (a00*a10 + a01*a11);
        float g11 = 0.5f * (a10*a10 + a11*a11);
        ok &= (g00 == g000) & (g01 == g010) & (g11 == g110);
        float gs  = 2.0f * g01;
        float det = g00*g11 - g01*g01;
        float wl  = ((k == 0 ? a : b) - lse) + 0.5f * logf(det);
        float m0 = mu[2*m], m1 = mu[2*m+1];
        float c3 = 2.0f*g00*m0 + gs*m1;
        float c4 = gs*m0 + 2.0f*g11*m1;
        float c5 = wl - (g00*m0*m0 + gs*m0*m1 + g11*m1*m1);
        int p = m >> 1, off = (m & 1);
        int bb = p * 12 + off;
        g_coef4[bb + 0]  = -g00 * L;
        g_coef4[bb + 2]  = -gs  * L;
        g_coef4[bb + 4]  = -g11 * L;
        g_coef4[bb + 6]  = c3 * L;
        g_coef4[bb + 8]  = c4 * L;
        g_coef4[bb + 10] = c5 * L;
        c3v[k] = c3; c4v[k] = c4; c5v[k] = c5;
        m0v[k] = m0; m1v[k] = m1; wlv[k] = wl;
    }
    if (!ok) s_flag = 0;

    float4 bbv;
    bbv.x = fminf(m0v[0], m0v[1]); bbv.y = fminf(m1v[0], m1v[1]);
    bbv.z = fmaxf(m0v[0], m0v[1]); bbv.w = fmaxf(m1v[0], m1v[1]);
    #pragma unroll
    for (int o = 16; o; o >>= 1) {
        bbv.x = fminf(bbv.x, __shfl_xor_sync(0xffffffffu, bbv.x, o));
        bbv.y = fminf(bbv.y, __shfl_xor_sync(0xffffffffu, bbv.y, o));
        bbv.z = fmaxf(bbv.z, __shfl_xor_sync(0xffffffffu, bbv.z, o));
        bbv.w = fmaxf(bbv.w, __shfl_xor_sync(0xffffffffu, bbv.w, o));
    }
    if (lane == 0) bb32[wid] = bbv;
    __syncthreads();
    if (t == 0) {
        float4 r = bb32[0];
        #pragma unroll
        for (int i = 1; i < 32; ++i) {
            r.x = fminf(r.x, bb32[i].x); r.y = fminf(r.y, bb32[i].y);
            r.z = fmaxf(r.z, bb32[i].z); r.w = fmaxf(r.w, bb32[i].w);
        }
        s_bbox[0] = r.x; s_bbox[1] = r.y; s_bbox[2] = r.z; s_bbox[3] = r.w;
    }
    __syncthreads();
    int uni = s_flag;

    if (uni) {
        float minx = s_bbox[0], miny = s_bbox[1];
        float sx = (float)CGRID / (s_bbox[2] - minx + 1e-5f);
        float sy = (float)CGRID / (s_bbox[3] - miny + 1e-5f);
        #pragma unroll
        for (int k = 0; k < 2; ++k) {
            int m = t + k * 1024;
            int cx = min(max((int)((m0v[k] - minx) * sx), 0), CGRID - 1);
            int cy = min(max((int)((m1v[k] - miny) * sy), 0), CGRID - 1);
            int c = cy * CGRID + cx;
            s_cell[m] = (unsigned char)c;
            atomicAdd(&s_hist[c], 1);
        }
        __syncthreads();
        int hv = 0, hisc = 0;
        if (t < CCELLS) {
            hv = s_hist[t];
            hisc = warp_iscan(hv, lane);
            if (lane == 31) w8[wid] = hisc;
        }
        __syncthreads();
        if (t == 0) {
            int acc = 0;
            #pragma unroll
            for (int i = 0; i < 8; ++i) { int x2 = w8[i]; w8[i] = acc; acc += x2; }
        }
        __syncthreads();
        if (t < CCELLS) {
            int base = w8[wid] + hisc - hv;
            s_start[t] = base;
            s_cur[t] = base;
        }
        __syncthreads();
        #pragma unroll
        for (int k = 0; k < 2; ++k) {
            int m = t + k * 1024;
            int c = s_cell[m];
            int pos = atomicAdd(&s_cur[c], 1);
            g_smu[pos] = make_float2(m0v[k], m1v[k]);
            g_swl[pos] = wlv[k] * L;
            int pp = pos >> 1, off = pos & 1;
            int bse = pp * 8;
            g_fast[bse + 0 + off] = c3v[k] * L;
            g_fast[bse + 2 + off] = c4v[k] * L;
            g_fast[bse + 4 + off] = c5v[k] * L;
        }
        __syncthreads();
        if (t < NTILE) {
            float xmn = 3e38f, ymn = 3e38f, xmx = -3e38f, ymx = -3e38f, wlm = -3e38f;
            #pragma unroll 4
            for (int j = 0; j < 16; ++j) {
                float2 q = g_smu[t * 16 + j];
                xmn = fminf(xmn, q.x); xmx = fmaxf(xmx, q.x);
                ymn = fminf(ymn, q.y); ymx = fmaxf(ymx, q.y);
                wlm = fmaxf(wlm, g_swl[t * 16 + j]);
            }
            g_tbb[t] = make_float4(xmn, ymn, xmx, ymx);
            g_twl[t] = wlm;
        }
        if (t < CCELLS) g_ctile[t] = min(s_start[t], M_COMP - 1) >> 4;
        __syncthreads();
        if (t < NSUP) {
            float4 r = g_tbb[t * 8];
            float wm = g_twl[t * 8];
            #pragma unroll
            for (int j = 1; j < 8; ++j) {
                float4 q = g_tbb[t * 8 + j];
                r.x = fminf(r.x, q.x); r.y = fminf(r.y, q.y);
                r.z = fmaxf(r.z, q.z); r.w = fmaxf(r.w, q.w);
                wm = fmaxf(wm, g_twl[t * 8 + j]);
            }
            g_sbb[t] = r;
            g_swlmx[t] = wm;
        }
        if (t == 0) {
            g_cg[0] = minx; g_cg[1] = miny; g_cg[2] = sx; g_cg[3] = sy;
            float tr2 = 0.5f * (g000 + g110);
            float dd  = 0.5f * (g000 - g110);
            float lam = fmaxf(tr2 - sqrtf(dd*dd + g010*g010), 0.0f);
            g_quad[0] = g000 * L; g_quad[1] = 2.0f * g010 * L;
            g_quad[2] = g110 * L; g_quad[3] = lam * L;
            g_uniform = 1;
        }
    } else if (t == 0) {
        g_uniform = 0;
    }
}

// ---------- K3: scatter, 4 samples/thread, one ST.128 per sample ----------
__global__ void k_scatter4(const float* __restrict__ sample) {
    int idx = blockIdx.x * blockDim.x + threadIdx.x;   // 32768 threads
    const float4* s4 = (const float4*)sample;
    float4 f1 = s4[idx];
    float4 f2 = s4[idx + 32768];
    int n0 = idx * 2;
    int n2 = (idx + 32768) * 2;
    int p0 = atomicAdd(&g_cellcur[sample_cell(f1.x, f1.y)], 1);
    g_sphl[p0] = make_float4(f1.x, f1.y, __int_as_float(n0), 0.f);
    int p1 = atomicAdd(&g_cellcur[sample_cell(f1.z, f1.w)], 1);
    g_sphl[p1] = make_float4(f1.z, f1.w, __int_as_float(n0 + 1), 0.f);
    int p2 = atomicAdd(&g_cellcur[sample_cell(f2.x, f2.y)], 1);
    g_sphl[p2] = make_float4(f2.x, f2.y, __int_as_float(n2), 0.f);
    int p3 = atomicAdd(&g_cellcur[sample_cell(f2.z, f2.w)], 1);
    g_sphl[p3] = make_float4(f2.z, f2.w, __int_as_float(n2 + 1), 0.f);
}

// ---------- K4: main — cyclic warp-chunk assignment for load balance ----------
__global__ __launch_bounds__(THREADS) void k_main(float* __restrict__ out) {
    extern __shared__ float dyn[];
    const float LN2 = 0.6931471805599453f;
    int t = threadIdx.x;
    int lane = t & 31, wrp = t >> 5;
    int uni = g_uniform;

    // chunk = 64 consecutive sorted samples handled by one warp.
    // Cyclic distribution: block b, warp w -> chunk b + w*GRID (spreads
    // dense-region chunks uniformly across CTAs).
    int chunk = blockIdx.x + wrp * GRID_MAIN;
    int gi = chunk * 64 + lane * 2;
    float4 fA = g_sphl[gi];
    float4 fB = g_sphl[gi + 1];
    float2 pa = make_float2(fA.x, fA.y);
    float2 pb = make_float2(fB.x, fB.y);
    int sA = __float_as_int(fA.z), sB = __float_as_int(fB.z);

    if (uni) {
        float4* d4 = (float4*)dyn;
        const float4* s4g = (const float4*)g_fast;
        #pragma unroll 1
        for (int i = t; i < NPAIR * 2; i += THREADS) d4[i] = s4g[i];
        float4* sb = (float4*)(dyn + 8192);
        if (t < NTILE) sb[t] = g_tbb[t];
        float* sw = dyn + 8704;
        if (t < NTILE) sw[t] = g_twl[t];
        int* sct = (int*)(dyn + 8832);
        #pragma unroll 1
        for (int i = t; i < CCELLS; i += THREADS) sct[i] = g_ctile[i];
        float4* ssb = (float4*)(dyn + 9088);
        if (t < NSUP) ssb[t] = g_sbb[t];
        float* ssw = dyn + 9152;
        if (t < NSUP) ssw[t] = g_swlmx[t];
        __syncthreads();
        uint32_t sbase = (uint32_t)__cvta_generic_to_shared(dyn);

        float q00 = g_quad[0], qs = g_quad[1], q11 = g_quad[2], lamL = g_quad[3];
        float KA = -(q00*pa.x*pa.x + qs*pa.x*pa.y + q11*pa.y*pa.y);
        float KB = -(q00*pb.x*pb.x + qs*pb.x*pb.y + q11*pb.y*pb.y);
        ull AX0 = pk2(pa.x), AX1 = pk2(pa.y);
        ull BX0 = pk2(pb.x), BX1 = pk2(pb.y);

        float minx = g_cg[0], miny = g_cg[1], csx = g_cg[2], csy = g_cg[3];
        int cx = min(max((int)((pa.x - minx) * csx), 0), CGRID - 1);
        int cy = min(max((int)((pa.y - miny) * csy), 0), CGRID - 1);
        int t0 = sct[cy * CGRID + cx];
        float ma = -3.0e38f, mb = -3.0e38f;
        {
            uint32_t base = sbase + (uint32_t)t0 * 256u;
            #pragma unroll
            for (int i = 0; i < 8; ++i) {
                uint32_t a = base + (uint32_t)i * 32u;
                ull U0, U1; lds2(U0, U1, a);
                ull U2 = ldsb64(a + 16u);
                ull va = f2fma(AX0, U0, f2fma(AX1, U1, U2));
                ull vb = f2fma(BX0, U0, f2fma(BX1, U1, U2));
                float x, y;
                unpk(va, x, y); ma = fmaxf(ma, fmaxf(x, y));
                unpk(vb, x, y); mb = fmaxf(mb, fmaxf(x, y));
            }
        }
        ull SA = 0ull, SB = 0ull;
        float thrA = KA - SKIP_BITS, thrB = KB - SKIP_BITS;

        for (int sup = 0; sup < NSUP; ++sup) {
            float4 SBB = ssb[sup];
            float swlm = ssw[sup];
            float dxA = fmaxf(fmaxf(SBB.x - pa.x, pa.x - SBB.z), 0.0f);
            float dyA = fmaxf(fmaxf(SBB.y - pa.y, pa.y - SBB.w), 0.0f);
            float dxB = fmaxf(fmaxf(SBB.x - pb.x, pb.x - SBB.z), 0.0f);
            float dyB = fmaxf(fmaxf(SBB.y - pb.y, pb.y - SBB.w), 0.0f);
            bool keepS = (swlm - lamL * (dxA*dxA + dyA*dyA) >= ma + thrA) |
                         (swlm - lamL * (dxB*dxB + dyB*dyB) >= mb + thrB);
            if (!__any_sync(0xffffffffu, keepS)) continue;

            #pragma unroll 1
            for (int tile = sup * 8; tile < sup * 8 + 8; ++tile) {
                float4 bb = sb[tile];
                float wlm = sw[tile];
                float dxa = fmaxf(fmaxf(bb.x - pa.x, pa.x - bb.z), 0.0f);
                float dya = fmaxf(fmaxf(bb.y - pa.y, pa.y - bb.w), 0.0f);
                float dxb = fmaxf(fmaxf(bb.x - pb.x, pb.x - bb.z), 0.0f);
                float dyb = fmaxf(fmaxf(bb.y - pb.y, pb.y - bb.w), 0.0f);
                bool keep = (wlm - lamL * (dxa*dxa + dya*dya) >= ma + thrA) |
                            (wlm - lamL * (dxb*dxb + dyb*dyb) >= mb + thrB);
                if (!__any_sync(0xffffffffu, keep)) continue;

                ull va[8], vb[8];
                float tma = -3.0e38f, tmb = -3.0e38f;
                uint32_t base = sbase + (uint32_t)tile * 256u;
                #pragma unroll
                for (int i = 0; i < 8; ++i) {
                    uint32_t a = base + (uint32_t)i * 32u;
                    ull U0, U1; lds2(U0, U1, a);
                    ull U2 = ldsb64(a + 16u);
                    va[i] = f2fma(AX0, U0, f2fma(AX1, U1, U2));
                    vb[i] = f2fma(BX0, U0, f2fma(BX1, U1, U2));
                    float x, y;
                    unpk(va[i], x, y); tma = fmaxf(tma, fmaxf(x, y));
                    unpk(vb[i], x, y); tmb = fmaxf(tmb, fmaxf(x, y));
                }
                float na = fmaxf(ma, tma), nb = fmaxf(mb, tmb);
                ull RA = pk2(ex2(ma - na)), RB = pk2(ex2(mb - nb));
                ull NMA = pk2(-na), NMB = pk2(-nb);
                ull TSA = 0ull, TSB = 0ull;
                #pragma unroll
                for (int i = 0; i < 8; ++i) {
                    ull da = f2add(va[i], NMA);
                    ull db = f2add(vb[i], NMB);
                    float x, y;
                    unpk(da, x, y); TSA = f2add(TSA, pk2p(ex2(x), ex2(y)));
                    unpk(db, x, y); TSB = f2add(TSB, pk2p(ex2(x), ex2(y)));
                }
                SA = f2fma(SA, RA, TSA);
                SB = f2fma(SB, RB, TSB);
                ma = na; mb = nb;
            }
        }
        float s0, s1;
        unpk(SA, s0, s1);
        out[sA] = (KA + ma + lg2(s0 + s1)) * LN2;
        unpk(SB, s0, s1);
        out[sB] = (KB + mb + lg2(s0 + s1)) * LN2;
    } else {
        // ---------- general path (unpruned, proven) ----------
        float4* d4 = (float4*)dyn;
        const float4* s4g = (const float4*)g_coef4;
        #pragma unroll 1
        for (int i = t; i < NPAIR * 3; i += THREADS) d4[i] = s4g[i];
        __syncthreads();
        uint32_t sbase = (uint32_t)__cvta_generic_to_shared(dyn);

        ull AF0 = pk2(pa.x*pa.x), AF1 = pk2(pa.x*pa.y), AF2 = pk2(pa.y*pa.y);
        ull AX0 = pk2(pa.x), AX1 = pk2(pa.y);
        ull BF0 = pk2(pb.x*pb.x), BF1 = pk2(pb.x*pb.y), BF2 = pk2(pb.y*pb.y);
        ull BX0 = pk2(pb.x), BX1 = pk2(pb.y);
        float ma = -3.0e38f, mb = -3.0e38f;
        ull SA = 0ull, SB = 0ull;
        for (int tt = 0; tt < NPAIR; tt += 8) {
            ull va[8], vb[8];
            float tma = -3.0e38f, tmb = -3.0e38f;
            uint32_t base = sbase + (uint32_t)tt * 48u;
            #pragma unroll
            for (int i = 0; i < 8; ++i) {
                uint32_t a = base + (uint32_t)i * 48u;
                ull C0, C1, C2, C3, C4, C5;
                lds2(C0, C1, a);
                lds2(C2, C3, a + 16u);
                lds2(C4, C5, a + 32u);
                va[i] = f2fma(AF0, C0, f2fma(AF1, C1, f2fma(AF2, C2,
                        f2fma(AX0, C3, f2fma(AX1, C4, C5)))));
                vb[i] = f2fma(BF0, C0, f2fma(BF1, C1, f2fma(BF2, C2,
                        f2fma(BX0, C3, f2fma(BX1, C4, C5)))));
                float x, y;
                unpk(va[i], x, y); tma = fmaxf(tma, fmaxf(x, y));
                unpk(vb[i], x, y); tmb = fmaxf(tmb, fmaxf(x, y));
            }
            float na = fmaxf(ma, tma), nb = fmaxf(mb, tmb);
            ull RA = pk2(ex2(ma - na)), RB = pk2(ex2(mb - nb));
            ull NMA = pk2(-na), NMB = pk2(-nb);
            ull TSA = 0ull, TSB = 0ull;
            #pragma unroll
            for (int i = 0; i < 8; ++i) {
                ull da = f2add(va[i], NMA);
                ull db = f2add(vb[i], NMB);
                float x, y;
                unpk(da, x, y); TSA = f2add(TSA, pk2p(ex2(x), ex2(y)));
                unpk(db, x, y); TSB = f2add(TSB, pk2p(ex2(x), ex2(y)));
            }
            SA = f2fma(SA, RA, TSA);
            SB = f2fma(SB, RB, TSB);
            ma = na; mb = nb;
        }
        float s0, s1;
        unpk(SA, s0, s1);
        out[sA] = (ma + lg2(s0 + s1)) * LN2;
        unpk(SB, s0, s1);
        out[sB] = (mb + lg2(s0 + s1)) * LN2;
    }
}

extern "C" void kernel_launch(void* const* d_in, const int* in_sizes, int n_in,
                              void* d_out, int out_size) {
    const float *sample = nullptr, *mu = nullptr, *A = nullptr, *w = nullptr;
    for (int i = 0; i < n_in; ++i) {
        int sz = in_sizes[i];
        const float* p = (const float*)d_in[i];
        if      (sz == N_SAMPLES * 2) sample = p;
        else if (sz == M_COMP * 2)    mu = p;
        else if (sz == M_COMP * 4)    A = p;
        else if (sz == M_COMP)        w = p;
    }
    cudaFuncSetAttribute(k_main,
                         cudaFuncAttributeMaxDynamicSharedMemorySize, SMEM_BYTES);
    cudaFuncSetAttribute(k_main,
                         cudaFuncAttributePreferredSharedMemoryCarveout, 100);
    k_hist4<<<N_SAMPLES / 4 / 256, 256>>>(sample);
    k_prepscan<<<1, 1024>>>(w, mu, A);
    k_scatter4<<<N_SAMPLES / 4 / 256, 256>>>(sample);
    k_main<<<GRID_MAIN, THREADS, SMEM_BYTES>>>((float*)d_out);
}

// round 17
// speedup vs baseline: 1.1236x; 1.1236x over previous
#include <cuda_runtime.h>
#include <cstdint>

#define N_SAMPLES 131072
#define M_COMP    2048
#define NPAIR     1024
#define NTILE     128                 // 16 components per tile
#define NSUP      16                  // 8 tiles per supertile
#define THREADS   256                 // k_main: 1 sample/thread
#define GRID_MAIN (N_SAMPLES/THREADS) // 512
#define SGRID     64
#define SCELLS    4096
#define CGRID     16
#define CCELLS    256
#define SKIP_BITS 22.0f
#define SMEM_BYTES 36864              // fast layout + meta (36.7 KB)

typedef unsigned long long ull;

// ---- device globals ----
__device__ float  g_coef4[NPAIR*12];
__device__ float  g_fast[NPAIR*8];
__device__ float2 g_smu[M_COMP];
__device__ float  g_swl[M_COMP];
__device__ float4 g_tbb[NTILE];
__device__ float  g_twl[NTILE];
__device__ float4 g_sbb[NSUP];
__device__ float  g_swlmx[NSUP];
__device__ int    g_ctile[CCELLS];
__device__ float  g_cg[4];
__device__ float  g_quad[4];
__device__ int    g_uniform;
__device__ int    g_cellcnt[SCELLS];   // zero-init at load; self-rezeroed each call
__device__ int    g_cellcur[SCELLS];
__device__ float4 g_sphl[N_SAMPLES];   // sorted: {x, y, idx_bits, 0}

// ---------- packed f32x2 helpers ----------
__device__ __forceinline__ ull pk2(float x) {
    ull r; asm("mov.b64 %0,{%1,%1};" : "=l"(r) : "f"(x)); return r;
}
__device__ __forceinline__ ull pk2p(float lo, float hi) {
    ull r; asm("mov.b64 %0,{%1,%2};" : "=l"(r) : "f"(lo), "f"(hi)); return r;
}
__device__ __forceinline__ void unpk(ull v, float& lo, float& hi) {
    asm("mov.b64 {%0,%1},%2;" : "=f"(lo), "=f"(hi) : "l"(v));
}
__device__ __forceinline__ ull f2fma(ull a, ull b, ull c) {
    ull d; asm("fma.rn.f32x2 %0,%1,%2,%3;" : "=l"(d) : "l"(a), "l"(b), "l"(c)); return d;
}
__device__ __forceinline__ ull f2add(ull a, ull b) {
    ull d; asm("add.rn.f32x2 %0,%1,%2;" : "=l"(d) : "l"(a), "l"(b)); return d;
}
__device__ __forceinline__ float ex2(float x) {
    float y; asm("ex2.approx.ftz.f32 %0,%1;" : "=f"(y) : "f"(x)); return y;
}
__device__ __forceinline__ float lg2(float x) {
    float y; asm("lg2.approx.f32 %0,%1;" : "=f"(y) : "f"(x)); return y;
}
__device__ __forceinline__ void lds2(ull& a, ull& b, uint32_t addr) {
    asm("ld.shared.v2.b64 {%0,%1},[%2];" : "=l"(a), "=l"(b) : "r"(addr));
}
__device__ __forceinline__ ull ldsb64(uint32_t addr) {
    ull a; asm("ld.shared.b64 %0,[%1];" : "=l"(a) : "r"(addr)); return a;
}
__device__ __forceinline__ int warp_iscan(int v, int lane) {
    #pragma unroll
    for (int o = 1; o < 32; o <<= 1) {
        int u = __shfl_up_sync(0xffffffffu, v, o);
        if (lane >= o) v += u;
    }
    return v;
}

__device__ __forceinline__ int sample_cell(float x, float y) {
    int cx = min(max((int)((x + 4.0f) * 8.0f), 0), SGRID - 1);
    int cy = min(max((int)((y + 4.0f) * 8.0f), 0), SGRID - 1);
    return cy * SGRID + cx;
}

// ---------- K1: histogram (4 samples/thread) ----------
__global__ void k_hist4(const float* __restrict__ sample) {
    int idx = blockIdx.x * blockDim.x + threadIdx.x;   // 32768 threads
    const float4* s4 = (const float4*)sample;
    float4 f1 = s4[idx];
    float4 f2 = s4[idx + 32768];
    atomicAdd(&g_cellcnt[sample_cell(f1.x, f1.y)], 1);
    atomicAdd(&g_cellcnt[sample_cell(f1.z, f1.w)], 1);
    atomicAdd(&g_cellcnt[sample_cell(f2.x, f2.y)], 1);
    atomicAdd(&g_cellcnt[sample_cell(f2.z, f2.w)], 1);
}

// ---------- K2: scan (parallel) + component prep (1 block, 1024 threads) ----------
__global__ void k_prepscan(const float* __restrict__ w,
                           const float* __restrict__ mu,
                           const float* __restrict__ Am) {
    __shared__ int wsum[32];
    __shared__ float r32[32];
    __shared__ float4 bb32[32];
    __shared__ float s_mx, s_lse, s_bbox[4];
    __shared__ int s_flag;
    __shared__ int s_hist[CCELLS];
    __shared__ int s_start[CCELLS];
    __shared__ int s_cur[CCELLS];
    __shared__ int w8[8];
    __shared__ unsigned char s_cell[M_COMP];
    const float L = 1.4426950408889634f;
    int t = threadIdx.x, lane = t & 31, wid = t >> 5;

    // ---- part 1: parallel exclusive scan of g_cellcnt (4 per thread) + rezero ----
    {
        int b4 = t * 4;
        int c0 = g_cellcnt[b4], c1 = g_cellcnt[b4+1], c2 = g_cellcnt[b4+2], c3 = g_cellcnt[b4+3];
        int sum = c0 + c1 + c2 + c3;
        int isc = warp_iscan(sum, lane);
        if (lane == 31) wsum[wid] = isc;
        __syncthreads();
        if (wid == 0) {
            int v = wsum[lane];
            v = warp_iscan(v, lane);
            wsum[lane] = v;
        }
        __syncthreads();
        int wbase = (wid > 0) ? wsum[wid - 1] : 0;
        int base = wbase + isc - sum;
        g_cellcur[b4]   = base;
        g_cellcur[b4+1] = base + c0;
        g_cellcur[b4+2] = base + c0 + c1;
        g_cellcur[b4+3] = base + c0 + c1 + c2;
        g_cellcnt[b4] = 0; g_cellcnt[b4+1] = 0; g_cellcnt[b4+2] = 0; g_cellcnt[b4+3] = 0;
    }
    __syncthreads();

    // ---- part 2: component prep (2 comps/thread) ----
    if (t == 0) s_flag = 1;
    if (t < CCELLS) s_hist[t] = 0;

    float a = w[t], b = w[t + 1024];

    float v = fmaxf(a, b);
    #pragma unroll
    for (int o = 16; o; o >>= 1) v = fmaxf(v, __shfl_xor_sync(0xffffffffu, v, o));
    if (lane == 0) r32[wid] = v;
    __syncthreads();
    if (wid == 0) {
        float m = r32[lane];
        #pragma unroll
        for (int o = 16; o; o >>= 1) m = fmaxf(m, __shfl_xor_sync(0xffffffffu, m, o));
        if (lane == 0) s_mx = m;
    }
    __syncthreads();
    float mx = s_mx;
    float e = expf(a - mx) + expf(b - mx);
    #pragma unroll
    for (int o = 16; o; o >>= 1) e += __shfl_xor_sync(0xffffffffu, e, o);
    __syncthreads();
    if (lane == 0) r32[wid] = e;
    __syncthreads();
    if (wid == 0) {
        float s = r32[lane];
        #pragma unroll
        for (int o = 16; o; o >>= 1) s += __shfl_xor_sync(0xffffffffu, s, o);
        if (lane == 0) s_lse = mx + logf(s);
    }
    __syncthreads();
    float lse = s_lse;

    float r00 = Am[0], r01 = Am[1], r10 = Am[2], r11 = Am[3];
    float g000 = 0.5f * (r00*r00 + r01*r01);
    float g010 = 0.5f * (r00*r10 + r01*r11);
    float g110 = 0.5f * (r10*r10 + r11*r11);

    float c3v[2], c4v[2], c5v[2], m0v[2], m1v[2], wlv[2];
    bool ok = true;
    #pragma unroll
    for (int k = 0; k < 2; ++k) {
        int m = t + k * 1024;
        float a00 = Am[4*m+0], a01 = Am[4*m+1], a10 = Am[4*m+2], a11 = Am[4*m+3];
        float g00 = 0.5f * (a00*a00 + a01*a01);
        float g01 = 0.5f * (a00*a10 + a01*a11);
        float g11 = 0.5f * (a10*a10 + a11*a11);
        ok &= (g00 == g000) & (g01 == g010) & (g11 == g110);
        float gs  = 2.0f * g01;
        float det = g00*g11 - g01*g01;
        float wl  = ((k == 0 ? a : b) - lse) + 0.5f * logf(det);
        float m0 = mu[2*m], m1 = mu[2*m+1];
        float c3 = 2.0f*g00*m0 + gs*m1;
        float c4 = gs*m0 + 2.0f*g11*m1;
        float c5 = wl - (g00*m0*m0 + gs*m0*m1 + g11*m1*m1);
        int p = m >> 1, off = (m & 1);
        int bb = p * 12 + off;
        g_coef4[bb + 0]  = -g00 * L;
        g_coef4[bb + 2]  = -gs  * L;
        g_coef4[bb + 4]  = -g11 * L;
        g_coef4[bb + 6]  = c3 * L;
        g_coef4[bb + 8]  = c4 * L;
        g_coef4[bb + 10] = c5 * L;
        c3v[k] = c3; c4v[k] = c4; c5v[k] = c5;
        m0v[k] = m0; m1v[k] = m1; wlv[k] = wl;
    }
    if (!ok) s_flag = 0;

    float4 bbv;
    bbv.x = fminf(m0v[0], m0v[1]); bbv.y = fminf(m1v[0], m1v[1]);
    bbv.z = fmaxf(m0v[0], m0v[1]); bbv.w = fmaxf(m1v[0], m1v[1]);
    #pragma unroll
    for (int o = 16; o; o >>= 1) {
        bbv.x = fminf(bbv.x, __shfl_xor_sync(0xffffffffu, bbv.x, o));
        bbv.y = fminf(bbv.y, __shfl_xor_sync(0xffffffffu, bbv.y, o));
        bbv.z = fmaxf(bbv.z, __shfl_xor_sync(0xffffffffu, bbv.z, o));
        bbv.w = fmaxf(bbv.w, __shfl_xor_sync(0xffffffffu, bbv.w, o));
    }
    if (lane == 0) bb32[wid] = bbv;
    __syncthreads();
    if (t == 0) {
        float4 r = bb32[0];
        #pragma unroll
        for (int i = 1; i < 32; ++i) {
            r.x = fminf(r.x, bb32[i].x); r.y = fminf(r.y, bb32[i].y);
            r.z = fmaxf(r.z, bb32[i].z); r.w = fmaxf(r.w, bb32[i].w);
        }
        s_bbox[0] = r.x; s_bbox[1] = r.y; s_bbox[2] = r.z; s_bbox[3] = r.w;
    }
    __syncthreads();
    int uni = s_flag;

    if (uni) {
        float minx = s_bbox[0], miny = s_bbox[1];
        float sx = (float)CGRID / (s_bbox[2] - minx + 1e-5f);
        float sy = (float)CGRID / (s_bbox[3] - miny + 1e-5f);
        #pragma unroll
        for (int k = 0; k < 2; ++k) {
            int m = t + k * 1024;
            int cx = min(max((int)((m0v[k] - minx) * sx), 0), CGRID - 1);
            int cy = min(max((int)((m1v[k] - miny) * sy), 0), CGRID - 1);
            int c = cy * CGRID + cx;
            s_cell[m] = (unsigned char)c;
            atomicAdd(&s_hist[c], 1);
        }
        __syncthreads();
        int hv = 0, hisc = 0;
        if (t < CCELLS) {
            hv = s_hist[t];
            hisc = warp_iscan(hv, lane);
            if (lane == 31) w8[wid] = hisc;
        }
        __syncthreads();
        if (t == 0) {
            int acc = 0;
            #pragma unroll
            for (int i = 0; i < 8; ++i) { int x2 = w8[i]; w8[i] = acc; acc += x2; }
        }
        __syncthreads();
        if (t < CCELLS) {
            int base = w8[wid] + hisc - hv;
            s_start[t] = base;
            s_cur[t] = base;
        }
        __syncthreads();
        #pragma unroll
        for (int k = 0; k < 2; ++k) {
            int m = t + k * 1024;
            int c = s_cell[m];
            int pos = atomicAdd(&s_cur[c], 1);
            g_smu[pos] = make_float2(m0v[k], m1v[k]);
            g_swl[pos] = wlv[k] * L;
            int pp = pos >> 1, off = pos & 1;
            int bse = pp * 8;
            g_fast[bse + 0 + off] = c3v[k] * L;
            g_fast[bse + 2 + off] = c4v[k] * L;
            g_fast[bse + 4 + off] = c5v[k] * L;
        }
        __syncthreads();
        if (t < NTILE) {
            float xmn = 3e38f, ymn = 3e38f, xmx = -3e38f, ymx = -3e38f, wlm = -3e38f;
            #pragma unroll 4
            for (int j = 0; j < 16; ++j) {
                float2 q = g_smu[t * 16 + j];
                xmn = fminf(xmn, q.x); xmx = fmaxf(xmx, q.x);
                ymn = fminf(ymn, q.y); ymx = fmaxf(ymx, q.y);
                wlm = fmaxf(wlm, g_swl[t * 16 + j]);
            }
            g_tbb[t] = make_float4(xmn, ymn, xmx, ymx);
            g_twl[t] = wlm;
        }
        if (t < CCELLS) g_ctile[t] = min(s_start[t], M_COMP - 1) >> 4;
        __syncthreads();
        if (t < NSUP) {
            float4 r = g_tbb[t * 8];
            float wm = g_twl[t * 8];
            #pragma unroll
            for (int j = 1; j < 8; ++j) {
                float4 q = g_tbb[t * 8 + j];
                r.x = fminf(r.x, q.x); r.y = fminf(r.y, q.y);
                r.z = fmaxf(r.z, q.z); r.w = fmaxf(r.w, q.w);
                wm = fmaxf(wm, g_twl[t * 8 + j]);
            }
            g_sbb[t] = r;
            g_swlmx[t] = wm;
        }
        if (t == 0) {
            g_cg[0] = minx; g_cg[1] = miny; g_cg[2] = sx; g_cg[3] = sy;
            float tr2 = 0.5f * (g000 + g110);
            float dd  = 0.5f * (g000 - g110);
            float lam = fmaxf(tr2 - sqrtf(dd*dd + g010*g010), 0.0f);
            g_quad[0] = g000 * L; g_quad[1] = 2.0f * g010 * L;
            g_quad[2] = g110 * L; g_quad[3] = lam * L;
            g_uniform = 1;
        }
    } else if (t == 0) {
        g_uniform = 0;
    }
}

// ---------- K3: scatter, 4 samples/thread, one ST.128 per sample ----------
__global__ void k_scatter4(const float* __restrict__ sample) {
    int idx = blockIdx.x * blockDim.x + threadIdx.x;   // 32768 threads
    const float4* s4 = (const float4*)sample;
    float4 f1 = s4[idx];
    float4 f2 = s4[idx + 32768];
    int n0 = idx * 2;
    int n2 = (idx + 32768) * 2;
    int p0 = atomicAdd(&g_cellcur[sample_cell(f1.x, f1.y)], 1);
    g_sphl[p0] = make_float4(f1.x, f1.y, __int_as_float(n0), 0.f);
    int p1 = atomicAdd(&g_cellcur[sample_cell(f1.z, f1.w)], 1);
    g_sphl[p1] = make_float4(f1.z, f1.w, __int_as_float(n0 + 1), 0.f);
    int p2 = atomicAdd(&g_cellcur[sample_cell(f2.x, f2.y)], 1);
    g_sphl[p2] = make_float4(f2.x, f2.y, __int_as_float(n2), 0.f);
    int p3 = atomicAdd(&g_cellcur[sample_cell(f2.z, f2.w)], 1);
    g_sphl[p3] = make_float4(f2.z, f2.w, __int_as_float(n2 + 1), 0.f);
}

// ---------- K4: main — 1 sample/thread, 256 threads, blocked mapping ----------
__global__ __launch_bounds__(THREADS) void k_main(float* __restrict__ out) {
    extern __shared__ float dyn[];
    const float LN2 = 0.6931471805599453f;
    int t = threadIdx.x;
    int uni = g_uniform;

    int gi = blockIdx.x * THREADS + t;          // warp spans 32 sorted samples
    float4 fA = g_sphl[gi];
    float2 p = make_float2(fA.x, fA.y);
    int sA = __float_as_int(fA.z);

    if (uni) {
        float4* d4 = (float4*)dyn;
        const float4* s4g = (const float4*)g_fast;
        #pragma unroll 1
        for (int i = t; i < NPAIR * 2; i += THREADS) d4[i] = s4g[i];
        float4* sb = (float4*)(dyn + 8192);
        if (t < NTILE) sb[t] = g_tbb[t];
        float* sw = dyn + 8704;
        if (t < NTILE) sw[t] = g_twl[t];
        int* sct = (int*)(dyn + 8832);
        if (t < CCELLS) sct[t] = g_ctile[t];
        float4* ssb = (float4*)(dyn + 9088);
        if (t < NSUP) ssb[t] = g_sbb[t];
        float* ssw = dyn + 9152;
        if (t < NSUP) ssw[t] = g_swlmx[t];
        __syncthreads();
        uint32_t sbase = (uint32_t)__cvta_generic_to_shared(dyn);

        float q00 = g_quad[0], qs = g_quad[1], q11 = g_quad[2], lamL = g_quad[3];
        float K = -(q00*p.x*p.x + qs*p.x*p.y + q11*p.y*p.y);
        ull X0 = pk2(p.x), X1 = pk2(p.y);

        float minx = g_cg[0], miny = g_cg[1], csx = g_cg[2], csy = g_cg[3];
        int cx = min(max((int)((p.x - minx) * csx), 0), CGRID - 1);
        int cy = min(max((int)((p.y - miny) * csy), 0), CGRID - 1);
        int t0 = sct[cy * CGRID + cx];
        float ma = -3.0e38f;
        {
            uint32_t base = sbase + (uint32_t)t0 * 256u;
            #pragma unroll
            for (int i = 0; i < 8; ++i) {
                uint32_t a = base + (uint32_t)i * 32u;
                ull U0, U1; lds2(U0, U1, a);
                ull U2 = ldsb64(a + 16u);
                ull va = f2fma(X0, U0, f2fma(X1, U1, U2));
                float x, y;
                unpk(va, x, y); ma = fmaxf(ma, fmaxf(x, y));
            }
        }
        ull SA = 0ull;
        float thr = K - SKIP_BITS;

        for (int sup = 0; sup < NSUP; ++sup) {
            float4 SBB = ssb[sup];
            float swlm = ssw[sup];
            float dx = fmaxf(fmaxf(SBB.x - p.x, p.x - SBB.z), 0.0f);
            float dy = fmaxf(fmaxf(SBB.y - p.y, p.y - SBB.w), 0.0f);
            bool keepS = (swlm - lamL * (dx*dx + dy*dy) >= ma + thr);
            if (!__any_sync(0xffffffffu, keepS)) continue;

            #pragma unroll 1
            for (int tile = sup * 8; tile < sup * 8 + 8; ++tile) {
                float4 bb = sb[tile];
                float wlm = sw[tile];
                float dxa = fmaxf(fmaxf(bb.x - p.x, p.x - bb.z), 0.0f);
                float dya = fmaxf(fmaxf(bb.y - p.y, p.y - bb.w), 0.0f);
                bool keep = (wlm - lamL * (dxa*dxa + dya*dya) >= ma + thr);
                if (!__any_sync(0xffffffffu, keep)) continue;

                ull va[8];
                float tm = -3.0e38f;
                uint32_t base = sbase + (uint32_t)tile * 256u;
                #pragma unroll
                for (int i = 0; i < 8; ++i) {
                    uint32_t a = base + (uint32_t)i * 32u;
                    ull U0, U1; lds2(U0, U1, a);
                    ull U2 = ldsb64(a + 16u);
                    va[i] = f2fma(X0, U0, f2fma(X1, U1, U2));
                    float x, y;
                    unpk(va[i], x, y); tm = fmaxf(tm, fmaxf(x, y));
                }
                float na = fmaxf(ma, tm);
                ull R  = pk2(ex2(ma - na));
                ull NM = pk2(-na);
                ull TS = 0ull;
                #pragma unroll
                for (int i = 0; i < 8; ++i) {
                    ull da = f2add(va[i], NM);
                    float x, y;
                    unpk(da, x, y); TS = f2add(TS, pk2p(ex2(x), ex2(y)));
                }
                SA = f2fma(SA, R, TS);
                ma = na;
            }
        }
        float s0, s1;
        unpk(SA, s0, s1);
        out[sA] = (K + ma + lg2(s0 + s1)) * LN2;
    } else {
        // ---------- general path: coefs straight from global (L2-resident) ----------
        ull F0 = pk2(p.x*p.x), F1 = pk2(p.x*p.y), F2 = pk2(p.y*p.y);
        ull X0 = pk2(p.x), X1 = pk2(p.y);
        float ma = -3.0e38f;
        ull SA = 0ull;
        const float4* cf = (const float4*)g_coef4;
        for (int tt = 0; tt < NPAIR; tt += 8) {
            ull va[8];
            float tm = -3.0e38f;
            #pragma unroll
            for (int i = 0; i < 8; ++i) {
                int pr = tt + i;
                float4 q0 = __ldg(&cf[pr*3 + 0]);
                float4 q1 = __ldg(&cf[pr*3 + 1]);
                float4 q2 = __ldg(&cf[pr*3 + 2]);
                ull C0 = pk2p(q0.x, q0.y), C1 = pk2p(q0.z, q0.w);
                ull C2 = pk2p(q1.x, q1.y), C3 = pk2p(q1.z, q1.w);
                ull C4 = pk2p(q2.x, q2.y), C5 = pk2p(q2.z, q2.w);
                va[i] = f2fma(F0, C0, f2fma(F1, C1, f2fma(F2, C2,
                        f2fma(X0, C3, f2fma(X1, C4, C5)))));
                float x, y;
                unpk(va[i], x, y); tm = fmaxf(tm, fmaxf(x, y));
            }
            float na = fmaxf(ma, tm);
            ull R  = pk2(ex2(ma - na));
            ull NM = pk2(-na);
            ull TS = 0ull;
            #pragma unroll
            for (int i = 0; i < 8; ++i) {
                ull da = f2add(va[i], NM);
                float x, y;
                unpk(da, x, y); TS = f2add(TS, pk2p(ex2(x), ex2(y)));
            }
            SA = f2fma(SA, R, TS);
            ma = na;
        }
        float s0, s1;
        unpk(SA, s0, s1);
        out[sA] = (ma + lg2(s0 + s1)) * LN2;
    }
}

extern "C" void kernel_launch(void* const* d_in, const int* in_sizes, int n_in,
                              void* d_out, int out_size) {
    const float *sample = nullptr, *mu = nullptr, *A = nullptr, *w = nullptr;
    for (int i = 0; i < n_in; ++i) {
        int sz = in_sizes[i];
        const float* p = (const float*)d_in[i];
        if      (sz == N_SAMPLES * 2) sample = p;
        else if (sz == M_COMP * 2)    mu = p;
        else if (sz == M_COMP * 4)    A = p;
        else if (sz == M_COMP)        w = p;
    }
    cudaFuncSetAttribute(k_main,
                         cudaFuncAttributeMaxDynamicSharedMemorySize, SMEM_BYTES);
    cudaFuncSetAttribute(k_main,
                         cudaFuncAttributePreferredSharedMemoryCarveout, 100);
    k_hist4<<<N_SAMPLES / 4 / 256, 256>>>(sample);
    k_prepscan<<<1, 1024>>>(w, mu, A);
    k_scatter4<<<N_SAMPLES / 4 / 256, 256>>>(sample);
    k_main<<<GRID_MAIN, THREADS, SMEM_BYTES>>>((float*)d_out);
}